// round 1
// baseline (speedup 1.0000x reference)
#include <cuda_runtime.h>
#include <cuda_bf16.h>
#include <cstdint>
#include <cstddef>

// ---------------------------------------------------------------------------
// PerceiverAttention, fp32 baseline.
//   B=16, S=2048, M=128, DIM=1024, HEADS=16, DIM_HEAD=64, INNER=1024
// Pipeline:
//   ln_kernel(x)      -> g_xn   (32768 x 1024)
//   ln_kernel(lat)    -> g_ln   ( 2048 x 1024)
//   gemm_nt           -> g_kv   (32768 x 2048) = xn @ Wkv^T
//   gemm_nt           -> g_q    ( 2048 x 1024) = ln @ Wq^T
//   attn_kernel       -> g_att  ( 2048 x 1024)
//   gemm_nt           -> d_out  ( 2048 x 1024) = att @ Wo^T
// ---------------------------------------------------------------------------

#define DIMC     1024
#define BATCH    16
#define SEQ      2048
#define NLAT     128
#define HEADS    16
#define DHEAD    64
#define INNER    1024
#define LNEPS    1e-5f

// Scratch (device globals: allocation-free per harness rules)
__device__ float g_xn[(size_t)BATCH * SEQ * DIMC];          // 128 MB
__device__ float g_ln[(size_t)BATCH * NLAT * DIMC];         //   8 MB
__device__ float g_kv[(size_t)BATCH * SEQ * 2 * INNER];     // 256 MB
__device__ float g_q [(size_t)BATCH * NLAT * INNER];        //   8 MB
__device__ float g_att[(size_t)BATCH * NLAT * INNER];       //   8 MB

// ---------------------------------------------------------------------------
// LayerNorm over last dim (1024). One block (256 threads) per row.
// ---------------------------------------------------------------------------
__global__ __launch_bounds__(256) void ln_kernel(
    const float* __restrict__ X, const float* __restrict__ G,
    const float* __restrict__ Bv, float* __restrict__ Y)
{
    const int row = blockIdx.x;
    const int t = threadIdx.x;
    const float4* xr = (const float4*)(X + (size_t)row * DIMC);
    float4 v = xr[t];

    float s = v.x + v.y + v.z + v.w;
    float q = v.x * v.x + v.y * v.y + v.z * v.z + v.w * v.w;
    #pragma unroll
    for (int o = 16; o > 0; o >>= 1) {
        s += __shfl_xor_sync(0xffffffffu, s, o);
        q += __shfl_xor_sync(0xffffffffu, q, o);
    }

    __shared__ float rs[8], rq[8];
    __shared__ float s_mu, s_r;
    if ((t & 31) == 0) { rs[t >> 5] = s; rq[t >> 5] = q; }
    __syncthreads();
    if (t == 0) {
        float S = 0.f, Q = 0.f;
        #pragma unroll
        for (int w = 0; w < 8; w++) { S += rs[w]; Q += rq[w]; }
        float mu  = S * (1.f / DIMC);
        float var = Q * (1.f / DIMC) - mu * mu;
        s_mu = mu;
        s_r  = rsqrtf(var + LNEPS);
    }
    __syncthreads();
    const float mu = s_mu, r = s_r;

    float4 g = ((const float4*)G)[t];
    float4 b = ((const float4*)Bv)[t];
    float4 o;
    o.x = (v.x - mu) * r * g.x + b.x;
    o.y = (v.y - mu) * r * g.y + b.y;
    o.z = (v.z - mu) * r * g.z + b.z;
    o.w = (v.w - mu) * r * g.w + b.w;
    ((float4*)(Y + (size_t)row * DIMC))[t] = o;
}

// ---------------------------------------------------------------------------
// C[M,N] = A[M,K] @ B[N,K]^T  (all fp32 row-major, K-major on both operands).
// Block tile 128x128, BK=8, 256 threads, 8x8 per-thread micro-tile.
// Requires M%128==0, N%128==0, K%8==0 (true for all three call sites).
// ---------------------------------------------------------------------------
#define GBM 128
#define GBN 128
#define GBK 8

__global__ __launch_bounds__(256) void gemm_nt(
    const float* __restrict__ A, const float* __restrict__ B,
    float* __restrict__ C, int M, int N, int K)
{
    __shared__ float As[GBK][GBM];
    __shared__ float Bs[GBK][GBN];

    const int tid = threadIdx.x;
    const int ty = tid >> 4;       // 0..15
    const int tx = tid & 15;       // 0..15
    const int rowBase = blockIdx.y * GBM;
    const int colBase = blockIdx.x * GBN;

    // load mapping: thread t loads one float4 of A-tile and one of B-tile.
    const int lrow = tid >> 1;            // 0..127
    const int lk   = (tid & 1) * 4;       // 0 or 4

    float acc[8][8];
    #pragma unroll
    for (int i = 0; i < 8; i++)
        #pragma unroll
        for (int j = 0; j < 8; j++) acc[i][j] = 0.f;

    for (int k0 = 0; k0 < K; k0 += GBK) {
        __syncthreads();
        float4 a = *(const float4*)(A + (size_t)(rowBase + lrow) * K + k0 + lk);
        float4 b = *(const float4*)(B + (size_t)(colBase + lrow) * K + k0 + lk);
        As[lk + 0][lrow] = a.x; As[lk + 1][lrow] = a.y;
        As[lk + 2][lrow] = a.z; As[lk + 3][lrow] = a.w;
        Bs[lk + 0][lrow] = b.x; Bs[lk + 1][lrow] = b.y;
        Bs[lk + 2][lrow] = b.z; Bs[lk + 3][lrow] = b.w;
        __syncthreads();

        #pragma unroll
        for (int kk = 0; kk < GBK; kk++) {
            float4 a0 = *(const float4*)&As[kk][ty * 8];
            float4 a1 = *(const float4*)&As[kk][ty * 8 + 4];
            float4 b0 = *(const float4*)&Bs[kk][tx * 8];
            float4 b1 = *(const float4*)&Bs[kk][tx * 8 + 4];
            float ra[8] = {a0.x, a0.y, a0.z, a0.w, a1.x, a1.y, a1.z, a1.w};
            float rb[8] = {b0.x, b0.y, b0.z, b0.w, b1.x, b1.y, b1.z, b1.w};
            #pragma unroll
            for (int i = 0; i < 8; i++)
                #pragma unroll
                for (int j = 0; j < 8; j++)
                    acc[i][j] += ra[i] * rb[j];
        }
    }

    #pragma unroll
    for (int i = 0; i < 8; i++) {
        float* cp = C + (size_t)(rowBase + ty * 8 + i) * N + colBase + tx * 8;
        float4 c0 = make_float4(acc[i][0], acc[i][1], acc[i][2], acc[i][3]);
        float4 c1 = make_float4(acc[i][4], acc[i][5], acc[i][6], acc[i][7]);
        *(float4*)(cp)     = c0;
        *(float4*)(cp + 4) = c1;
    }
}

// ---------------------------------------------------------------------------
// Attention: one block per (b,h), 128 threads; thread i owns latent row i.
// Online softmax over S in chunks of 32. q pre-scaled by DHEAD^-0.5.
// smem: qT[64][128] (32KB) + k chunk (8KB) + v chunk (8KB) = 48KB.
// ---------------------------------------------------------------------------
__global__ __launch_bounds__(128) void attn_kernel(
    const float* __restrict__ Q, const float* __restrict__ KV,
    float* __restrict__ O)
{
    __shared__ float  qT[DHEAD][NLAT];     // qT[d][i]
    __shared__ float4 ks4[32][16];         // k chunk: [j][d4]
    __shared__ float4 vs4[32][16];         // v chunk: [j][d4]

    const int i = threadIdx.x;             // latent row 0..127
    const int b = blockIdx.x >> 4;
    const int h = blockIdx.x & 15;
    const float scale = 0.125f;            // 64^-0.5

    // load + transpose + scale q row
    const float4* qrow = (const float4*)(Q + ((size_t)(b * NLAT + i)) * INNER + h * DHEAD);
    #pragma unroll
    for (int d4 = 0; d4 < 16; d4++) {
        float4 v = __ldg(qrow + d4);
        qT[4 * d4 + 0][i] = v.x * scale;
        qT[4 * d4 + 1][i] = v.y * scale;
        qT[4 * d4 + 2][i] = v.z * scale;
        qT[4 * d4 + 3][i] = v.w * scale;
    }

    float m = -1e30f, l = 0.f;
    float4 acc[16];
    #pragma unroll
    for (int d4 = 0; d4 < 16; d4++) acc[d4] = make_float4(0.f, 0.f, 0.f, 0.f);

    const float* kbase = KV + (size_t)(b * SEQ) * (2 * INNER) + h * DHEAD;

    for (int s0 = 0; s0 < SEQ; s0 += 32) {
        __syncthreads();
        const float* kc = kbase + (size_t)s0 * (2 * INNER);
        #pragma unroll
        for (int c = 0; c < 4; c++) {
            int lin = c * 128 + i;                 // 0..511 float4 slots
            int r = lin >> 4, cc = lin & 15;
            const float4* src = (const float4*)(kc + (size_t)r * (2 * INNER)) + cc;
            ks4[r][cc] = __ldg(src);
            vs4[r][cc] = __ldg(src + (INNER / 4)); // v = +1024 floats in same row
        }
        __syncthreads();

        // logits for 32 keys
        float lo[32];
        #pragma unroll
        for (int j = 0; j < 32; j++) lo[j] = 0.f;
        for (int d4 = 0; d4 < 16; d4++) {
            float q0 = qT[4 * d4 + 0][i];
            float q1 = qT[4 * d4 + 1][i];
            float q2 = qT[4 * d4 + 2][i];
            float q3 = qT[4 * d4 + 3][i];
            #pragma unroll
            for (int j = 0; j < 32; j++) {
                float4 k4 = ks4[j][d4];
                lo[j] += q0 * k4.x + q1 * k4.y + q2 * k4.z + q3 * k4.w;
            }
        }

        // online softmax update
        float nm = m;
        #pragma unroll
        for (int j = 0; j < 32; j++) nm = fmaxf(nm, lo[j]);
        float corr = __expf(m - nm);
        l *= corr;
        #pragma unroll
        for (int d4 = 0; d4 < 16; d4++) {
            acc[d4].x *= corr; acc[d4].y *= corr;
            acc[d4].z *= corr; acc[d4].w *= corr;
        }
        float p[32];
        #pragma unroll
        for (int j = 0; j < 32; j++) { p[j] = __expf(lo[j] - nm); l += p[j]; }
        m = nm;

        // acc += p @ V
        #pragma unroll
        for (int j = 0; j < 32; j++) {
            float pj = p[j];
            #pragma unroll
            for (int d4 = 0; d4 < 16; d4++) {
                float4 v4 = vs4[j][d4];
                acc[d4].x += pj * v4.x; acc[d4].y += pj * v4.y;
                acc[d4].z += pj * v4.z; acc[d4].w += pj * v4.w;
            }
        }
    }

    const float inv = 1.f / l;
    float4* orow = (float4*)(O + ((size_t)(b * NLAT + i)) * INNER + h * DHEAD);
    #pragma unroll
    for (int d4 = 0; d4 < 16; d4++) {
        float4 a = acc[d4];
        a.x *= inv; a.y *= inv; a.z *= inv; a.w *= inv;
        orow[d4] = a;
    }
}

// ---------------------------------------------------------------------------
// launch
// ---------------------------------------------------------------------------
extern "C" void kernel_launch(void* const* d_in, const int* in_sizes, int n_in,
                              void* d_out, int out_size)
{
    (void)in_sizes; (void)n_in; (void)out_size;
    const float* x   = (const float*)d_in[0];
    const float* lat = (const float*)d_in[1];
    const float* gx  = (const float*)d_in[2];
    const float* bx  = (const float*)d_in[3];
    const float* gl  = (const float*)d_in[4];
    const float* bl  = (const float*)d_in[5];
    const float* Wq  = (const float*)d_in[6];
    const float* Wkv = (const float*)d_in[7];
    const float* Wo  = (const float*)d_in[8];
    float* out = (float*)d_out;

    float *p_xn, *p_ln, *p_kv, *p_q, *p_att;
    cudaGetSymbolAddress((void**)&p_xn,  g_xn);
    cudaGetSymbolAddress((void**)&p_ln,  g_ln);
    cudaGetSymbolAddress((void**)&p_kv,  g_kv);
    cudaGetSymbolAddress((void**)&p_q,   g_q);
    cudaGetSymbolAddress((void**)&p_att, g_att);

    const int rowsX = BATCH * SEQ;    // 32768
    const int rowsL = BATCH * NLAT;   // 2048

    ln_kernel<<<rowsX, 256>>>(x,   gx, bx, p_xn);
    ln_kernel<<<rowsL, 256>>>(lat, gl, bl, p_ln);

    // kv = xn @ Wkv^T : (32768 x 1024) x (2048 x 1024)^T
    gemm_nt<<<dim3(2 * INNER / GBN, rowsX / GBM), 256>>>(p_xn, Wkv, p_kv,
                                                         rowsX, 2 * INNER, DIMC);
    // q = ln @ Wq^T : (2048 x 1024) x (1024 x 1024)^T
    gemm_nt<<<dim3(INNER / GBN, rowsL / GBM), 256>>>(p_ln, Wq, p_q,
                                                     rowsL, INNER, DIMC);

    attn_kernel<<<BATCH * HEADS, 128>>>(p_q, p_kv, p_att);

    // out = att @ Wo^T : (2048 x 1024) x (1024 x 1024)^T
    gemm_nt<<<dim3(DIMC / GBN, rowsL / GBM), 256>>>(p_att, Wo, out,
                                                    rowsL, DIMC, INNER);
}

// round 3
// speedup vs baseline: 2.3563x; 2.3563x over previous
#include <cuda_runtime.h>
#include <cuda_bf16.h>
#include <cstdint>
#include <cstddef>

// ---------------------------------------------------------------------------
// PerceiverAttention: tf32 mma.sync GEMMs (sm_100 baseline target) + fp32 attn.
//   B=16, S=2048, M=128, DIM=1024, HEADS=16, DIM_HEAD=64, INNER=1024
// Pipeline:
//   ln_kernel(x)      -> g_xn   (tf32-rounded fp32)
//   ln_kernel(lat)    -> g_ln
//   tf32_round        -> g_wkv, g_wq, g_wo (pre-rounded weights)
//   gemm_tf32         -> g_kv   = xn @ Wkv^T   [tensor core mma.sync]
//   gemm_tf32         -> g_q    = ln @ Wq^T
//   attn_kernel       -> g_att  (tf32-rounded)
//   gemm_tf32         -> d_out  = att @ Wo^T
// ---------------------------------------------------------------------------

#define DIMC     1024
#define BATCH    16
#define SEQ      2048
#define NLAT     128
#define HEADS    16
#define DHEAD    64
#define INNER    1024
#define LNEPS    1e-5f
#define GK       1024            // K for all GEMMs

__device__ float g_xn [(size_t)BATCH * SEQ * DIMC];
__device__ float g_ln [(size_t)BATCH * NLAT * DIMC];
__device__ float g_kv [(size_t)BATCH * SEQ * 2 * INNER];
__device__ float g_q  [(size_t)BATCH * NLAT * INNER];
__device__ float g_att[(size_t)BATCH * NLAT * INNER];
__device__ float g_wq [(size_t)INNER * DIMC];
__device__ float g_wkv[(size_t)2 * INNER * DIMC];
__device__ float g_wo [(size_t)DIMC * INNER];

__device__ __forceinline__ float tf32_rn(float x) {
    uint32_t u;
    asm("cvt.rna.tf32.f32 %0, %1;" : "=r"(u) : "f"(x));
    return __uint_as_float(u);
}

// ===========================================================================
// tf32 rounding pass for weights
// ===========================================================================
__global__ __launch_bounds__(256) void tf32_round_kernel(
    const float4* __restrict__ src, float4* __restrict__ dst)
{
    int i = blockIdx.x * 256 + threadIdx.x;
    float4 v = src[i];
    v.x = tf32_rn(v.x); v.y = tf32_rn(v.y);
    v.z = tf32_rn(v.z); v.w = tf32_rn(v.w);
    dst[i] = v;
}

// ===========================================================================
// LayerNorm over last dim (1024). One block (256 threads) per row.
// Output rounded to tf32 (feeds tensor-core GEMMs).
// ===========================================================================
__global__ __launch_bounds__(256) void ln_kernel(
    const float* __restrict__ X, const float* __restrict__ G,
    const float* __restrict__ Bv, float* __restrict__ Y)
{
    const int row = blockIdx.x;
    const int t = threadIdx.x;
    const float4* xr = (const float4*)(X + (size_t)row * DIMC);
    float4 v = xr[t];

    float s = v.x + v.y + v.z + v.w;
    float q = v.x * v.x + v.y * v.y + v.z * v.z + v.w * v.w;
    #pragma unroll
    for (int o = 16; o > 0; o >>= 1) {
        s += __shfl_xor_sync(0xffffffffu, s, o);
        q += __shfl_xor_sync(0xffffffffu, q, o);
    }
    __shared__ float rs[8], rq[8];
    __shared__ float s_mu, s_r;
    if ((t & 31) == 0) { rs[t >> 5] = s; rq[t >> 5] = q; }
    __syncthreads();
    if (t == 0) {
        float S = 0.f, Q = 0.f;
        #pragma unroll
        for (int w = 0; w < 8; w++) { S += rs[w]; Q += rq[w]; }
        float mu  = S * (1.f / DIMC);
        float var = Q * (1.f / DIMC) - mu * mu;
        s_mu = mu;
        s_r  = rsqrtf(var + LNEPS);
    }
    __syncthreads();
    const float mu = s_mu, r = s_r;

    float4 g = ((const float4*)G)[t];
    float4 b = ((const float4*)Bv)[t];
    float4 o;
    o.x = tf32_rn((v.x - mu) * r * g.x + b.x);
    o.y = tf32_rn((v.y - mu) * r * g.y + b.y);
    o.z = tf32_rn((v.z - mu) * r * g.z + b.z);
    o.w = tf32_rn((v.w - mu) * r * g.w + b.w);
    ((float4*)(Y + (size_t)row * DIMC))[t] = o;
}

// ===========================================================================
// tf32 mma.sync GEMM: C[M,N] = A[M,1024] @ B[N,1024]^T, fp32 out.
// 128x128 block tile, 8 warps (warp tile 64x32), BK=32, 3-stage cp.async.
// A/B inputs must be pre-rounded to tf32. M%128==0, N%128==0.
// ===========================================================================
#define AS_STRIDE 36                     // 32 + 4 pad floats
#define TILE_FLOATS (128 * AS_STRIDE)    // 4608 floats, 18432 B
#define STAGE_FLOATS (2 * TILE_FLOATS)   // A + B
#define GEMM_SMEM (3 * STAGE_FLOATS * 4) // 110592 B
#define KITERS (GK / 32)                 // 32

__device__ __forceinline__ void stage_copy(
    const float* __restrict__ Ab, const float* __restrict__ Bb,
    uint32_t sA, uint32_t sB, int k0, int tid)
{
    #pragma unroll
    for (int i = 0; i < 4; i++) {
        const int slot = tid + i * 256;     // 0..1023
        const int r = slot >> 3;            // row 0..127
        const int c = slot & 7;             // float4 col 0..7
        const float* ga = Ab + (size_t)r * GK + k0 + c * 4;
        const float* gb = Bb + (size_t)r * GK + k0 + c * 4;
        uint32_t da = sA + (uint32_t)(r * AS_STRIDE + c * 4) * 4;
        uint32_t db = sB + (uint32_t)(r * AS_STRIDE + c * 4) * 4;
        asm volatile("cp.async.cg.shared.global [%0], [%1], 16;" :: "r"(da), "l"(ga));
        asm volatile("cp.async.cg.shared.global [%0], [%1], 16;" :: "r"(db), "l"(gb));
    }
}

__device__ __forceinline__ void mma_tf32(
    float* c, const uint32_t* a, const uint32_t* b)
{
    asm volatile(
        "mma.sync.aligned.m16n8k8.row.col.f32.tf32.tf32.f32 "
        "{%0,%1,%2,%3}, {%4,%5,%6,%7}, {%8,%9}, {%0,%1,%2,%3};"
        : "+f"(c[0]), "+f"(c[1]), "+f"(c[2]), "+f"(c[3])
        : "r"(a[0]), "r"(a[1]), "r"(a[2]), "r"(a[3]), "r"(b[0]), "r"(b[1]));
}

__global__ __launch_bounds__(256) void gemm_tf32(
    const float* __restrict__ A, const float* __restrict__ B,
    float* __restrict__ C, int Nld)
{
    extern __shared__ __align__(16) float sm[];
    const int tid  = threadIdx.x;
    const int wid  = tid >> 5;
    const int lane = tid & 31;
    const int wm = wid >> 2;           // 0..1 (64 rows each)
    const int wn = wid & 3;            // 0..3 (32 cols each)
    const int rowBase = blockIdx.y * 128;
    const int colBase = blockIdx.x * 128;
    const float* Ab = A + (size_t)rowBase * GK;
    const float* Bb = B + (size_t)colBase * GK;

    const uint32_t sbase = (uint32_t)__cvta_generic_to_shared(sm);

    float acc[4][4][4];
    #pragma unroll
    for (int i = 0; i < 4; i++)
        #pragma unroll
        for (int j = 0; j < 4; j++)
            #pragma unroll
            for (int r = 0; r < 4; r++) acc[i][j][r] = 0.f;

    // prologue: stages 0, 1
    stage_copy(Ab, Bb, sbase, sbase + TILE_FLOATS * 4, 0, tid);
    asm volatile("cp.async.commit_group;" ::: "memory");
    stage_copy(Ab, Bb, sbase + STAGE_FLOATS * 4,
               sbase + (STAGE_FLOATS + TILE_FLOATS) * 4, 32, tid);
    asm volatile("cp.async.commit_group;" ::: "memory");

    const int lr = lane >> 2;    // 0..7
    const int lc = lane & 3;     // 0..3

    #pragma unroll 1
    for (int t = 0; t < KITERS; t++) {
        if (t < KITERS - 2) {
            asm volatile("cp.async.wait_group 1;" ::: "memory");
            __syncthreads();
            const int s2 = (t + 2) % 3;
            stage_copy(Ab, Bb, sbase + (s2 * STAGE_FLOATS) * 4,
                       sbase + (s2 * STAGE_FLOATS + TILE_FLOATS) * 4,
                       (t + 2) * 32, tid);
            asm volatile("cp.async.commit_group;" ::: "memory");
        } else if (t == KITERS - 2) {
            asm volatile("cp.async.wait_group 0;" ::: "memory");
            __syncthreads();
        }

        const float* As = sm + (t % 3) * STAGE_FLOATS;
        const float* Bs = As + TILE_FLOATS;

        #pragma unroll
        for (int kk = 0; kk < 4; kk++) {
            const int k = kk * 8 + lc;
            uint32_t a[4][4], b[4][2];
            #pragma unroll
            for (int mt = 0; mt < 4; mt++) {
                const int m = wm * 64 + mt * 16 + lr;
                a[mt][0] = __float_as_uint(As[m * AS_STRIDE + k]);
                a[mt][1] = __float_as_uint(As[(m + 8) * AS_STRIDE + k]);
                a[mt][2] = __float_as_uint(As[m * AS_STRIDE + k + 4]);
                a[mt][3] = __float_as_uint(As[(m + 8) * AS_STRIDE + k + 4]);
            }
            #pragma unroll
            for (int nt = 0; nt < 4; nt++) {
                const int n = wn * 32 + nt * 8 + lr;
                b[nt][0] = __float_as_uint(Bs[n * AS_STRIDE + k]);
                b[nt][1] = __float_as_uint(Bs[n * AS_STRIDE + k + 4]);
            }
            #pragma unroll
            for (int mt = 0; mt < 4; mt++)
                #pragma unroll
                for (int nt = 0; nt < 4; nt++)
                    mma_tf32(acc[mt][nt], a[mt], b[nt]);
        }
    }

    // epilogue
    #pragma unroll
    for (int mt = 0; mt < 4; mt++) {
        #pragma unroll
        for (int nt = 0; nt < 4; nt++) {
            const int row = rowBase + wm * 64 + mt * 16 + lr;
            const int col = colBase + wn * 32 + nt * 8 + 2 * lc;
            float2 lo = make_float2(acc[mt][nt][0], acc[mt][nt][1]);
            float2 hi = make_float2(acc[mt][nt][2], acc[mt][nt][3]);
            *(float2*)(C + (size_t)row * Nld + col)       = lo;
            *(float2*)(C + (size_t)(row + 8) * Nld + col) = hi;
        }
    }
}

// ===========================================================================
// Attention: one block per (b,h), 128 threads; thread i owns latent row i.
// Online softmax over S in chunks of 32. Output rounded to tf32.
// ===========================================================================
__global__ __launch_bounds__(128) void attn_kernel(
    const float* __restrict__ Q, const float* __restrict__ KV,
    float* __restrict__ O)
{
    __shared__ float  qT[DHEAD][NLAT];
    __shared__ float4 ks4[32][16];
    __shared__ float4 vs4[32][16];

    const int i = threadIdx.x;
    const int b = blockIdx.x >> 4;
    const int h = blockIdx.x & 15;
    const float scale = 0.125f;

    const float4* qrow = (const float4*)(Q + ((size_t)(b * NLAT + i)) * INNER + h * DHEAD);
    #pragma unroll
    for (int d4 = 0; d4 < 16; d4++) {
        float4 v = __ldg(qrow + d4);
        qT[4 * d4 + 0][i] = v.x * scale;
        qT[4 * d4 + 1][i] = v.y * scale;
        qT[4 * d4 + 2][i] = v.z * scale;
        qT[4 * d4 + 3][i] = v.w * scale;
    }

    float m = -1e30f, l = 0.f;
    float4 acc[16];
    #pragma unroll
    for (int d4 = 0; d4 < 16; d4++) acc[d4] = make_float4(0.f, 0.f, 0.f, 0.f);

    const float* kbase = KV + (size_t)(b * SEQ) * (2 * INNER) + h * DHEAD;

    for (int s0 = 0; s0 < SEQ; s0 += 32) {
        __syncthreads();
        const float* kc = kbase + (size_t)s0 * (2 * INNER);
        #pragma unroll
        for (int c = 0; c < 4; c++) {
            int lin = c * 128 + i;
            int r = lin >> 4, cc = lin & 15;
            const float4* src = (const float4*)(kc + (size_t)r * (2 * INNER)) + cc;
            ks4[r][cc] = __ldg(src);
            vs4[r][cc] = __ldg(src + (INNER / 4));
        }
        __syncthreads();

        float lo[32];
        #pragma unroll
        for (int j = 0; j < 32; j++) lo[j] = 0.f;
        for (int d4 = 0; d4 < 16; d4++) {
            float q0 = qT[4 * d4 + 0][i];
            float q1 = qT[4 * d4 + 1][i];
            float q2 = qT[4 * d4 + 2][i];
            float q3 = qT[4 * d4 + 3][i];
            #pragma unroll
            for (int j = 0; j < 32; j++) {
                float4 k4 = ks4[j][d4];
                lo[j] += q0 * k4.x + q1 * k4.y + q2 * k4.z + q3 * k4.w;
            }
        }

        float nm = m;
        #pragma unroll
        for (int j = 0; j < 32; j++) nm = fmaxf(nm, lo[j]);
        float corr = __expf(m - nm);
        l *= corr;
        #pragma unroll
        for (int d4 = 0; d4 < 16; d4++) {
            acc[d4].x *= corr; acc[d4].y *= corr;
            acc[d4].z *= corr; acc[d4].w *= corr;
        }
        float p[32];
        #pragma unroll
        for (int j = 0; j < 32; j++) { p[j] = __expf(lo[j] - nm); l += p[j]; }
        m = nm;

        #pragma unroll
        for (int j = 0; j < 32; j++) {
            float pj = p[j];
            #pragma unroll
            for (int d4 = 0; d4 < 16; d4++) {
                float4 v4 = vs4[j][d4];
                acc[d4].x += pj * v4.x; acc[d4].y += pj * v4.y;
                acc[d4].z += pj * v4.z; acc[d4].w += pj * v4.w;
            }
        }
    }

    const float inv = 1.f / l;
    float4* orow = (float4*)(O + ((size_t)(b * NLAT + i)) * INNER + h * DHEAD);
    #pragma unroll
    for (int d4 = 0; d4 < 16; d4++) {
        float4 a = acc[d4];
        a.x = tf32_rn(a.x * inv); a.y = tf32_rn(a.y * inv);
        a.z = tf32_rn(a.z * inv); a.w = tf32_rn(a.w * inv);
        orow[d4] = a;
    }
}

// ===========================================================================
// launch
// ===========================================================================
extern "C" void kernel_launch(void* const* d_in, const int* in_sizes, int n_in,
                              void* d_out, int out_size)
{
    (void)in_sizes; (void)n_in; (void)out_size;
    const float* x   = (const float*)d_in[0];
    const float* lat = (const float*)d_in[1];
    const float* gx  = (const float*)d_in[2];
    const float* bx  = (const float*)d_in[3];
    const float* gl  = (const float*)d_in[4];
    const float* bl  = (const float*)d_in[5];
    const float* Wq  = (const float*)d_in[6];
    const float* Wkv = (const float*)d_in[7];
    const float* Wo  = (const float*)d_in[8];
    float* out = (float*)d_out;

    float *p_xn, *p_ln, *p_kv, *p_q, *p_att, *p_wq, *p_wkv, *p_wo;
    cudaGetSymbolAddress((void**)&p_xn,  g_xn);
    cudaGetSymbolAddress((void**)&p_ln,  g_ln);
    cudaGetSymbolAddress((void**)&p_kv,  g_kv);
    cudaGetSymbolAddress((void**)&p_q,   g_q);
    cudaGetSymbolAddress((void**)&p_att, g_att);
    cudaGetSymbolAddress((void**)&p_wq,  g_wq);
    cudaGetSymbolAddress((void**)&p_wkv, g_wkv);
    cudaGetSymbolAddress((void**)&p_wo,  g_wo);

    static int smem_set = 0;
    if (!smem_set) {
        cudaFuncSetAttribute(gemm_tf32, cudaFuncAttributeMaxDynamicSharedMemorySize, GEMM_SMEM);
        smem_set = 1;
    }

    const int rowsX = BATCH * SEQ;    // 32768
    const int rowsL = BATCH * NLAT;   // 2048

    ln_kernel<<<rowsX, 256>>>(x,   gx, bx, p_xn);
    ln_kernel<<<rowsL, 256>>>(lat, gl, bl, p_ln);

    tf32_round_kernel<<<(2 * INNER * DIMC) / 1024, 256>>>((const float4*)Wkv, (float4*)p_wkv);
    tf32_round_kernel<<<(INNER * DIMC) / 1024, 256>>>((const float4*)Wq, (float4*)p_wq);
    tf32_round_kernel<<<(DIMC * INNER) / 1024, 256>>>((const float4*)Wo, (float4*)p_wo);

    // kv = xn @ Wkv^T : (32768 x 2048)
    gemm_tf32<<<dim3(2 * INNER / 128, rowsX / 128), 256, GEMM_SMEM>>>(p_xn, p_wkv, p_kv, 2 * INNER);
    // q = ln @ Wq^T : (2048 x 1024)
    gemm_tf32<<<dim3(INNER / 128, rowsL / 128), 256, GEMM_SMEM>>>(p_ln, p_wq, p_q, INNER);

    attn_kernel<<<BATCH * HEADS, 128>>>(p_q, p_kv, p_att);

    // out = att @ Wo^T : (2048 x 1024)
    gemm_tf32<<<dim3(DIMC / 128, rowsL / 128), 256, GEMM_SMEM>>>(p_att, p_wo, out, DIMC);
}

// round 4
// speedup vs baseline: 3.7149x; 1.5766x over previous
#include <cuda_runtime.h>
#include <cuda_bf16.h>
#include <cstdint>
#include <cstddef>

// ---------------------------------------------------------------------------
// PerceiverAttention: tf32 mma.sync GEMMs + tf32 mma flash-attention.
//   B=16, S=2048, M=128, DIM=1024, HEADS=16, DIM_HEAD=64, INNER=1024
// ---------------------------------------------------------------------------

#define DIMC     1024
#define BATCH    16
#define SEQ      2048
#define NLAT     128
#define HEADS    16
#define DHEAD    64
#define INNER    1024
#define LNEPS    1e-5f
#define GK       1024

__device__ float g_xn [(size_t)BATCH * SEQ * DIMC];
__device__ float g_ln [(size_t)BATCH * NLAT * DIMC];
__device__ float g_kv [(size_t)BATCH * SEQ * 2 * INNER];
__device__ float g_q  [(size_t)BATCH * NLAT * INNER];
__device__ float g_att[(size_t)BATCH * NLAT * INNER];
__device__ float g_wq [(size_t)INNER * DIMC];
__device__ float g_wkv[(size_t)2 * INNER * DIMC];
__device__ float g_wo [(size_t)DIMC * INNER];

__device__ __forceinline__ float tf32_rn(float x) {
    uint32_t u;
    asm("cvt.rna.tf32.f32 %0, %1;" : "=r"(u) : "f"(x));
    return __uint_as_float(u);
}

__device__ __forceinline__ void mma_tf32(
    float* c, const uint32_t* a, const uint32_t* b)
{
    asm volatile(
        "mma.sync.aligned.m16n8k8.row.col.f32.tf32.tf32.f32 "
        "{%0,%1,%2,%3}, {%4,%5,%6,%7}, {%8,%9}, {%0,%1,%2,%3};"
        : "+f"(c[0]), "+f"(c[1]), "+f"(c[2]), "+f"(c[3])
        : "r"(a[0]), "r"(a[1]), "r"(a[2]), "r"(a[3]), "r"(b[0]), "r"(b[1]));
}

// ===========================================================================
// tf32 rounding pass for weights
// ===========================================================================
__global__ __launch_bounds__(256) void tf32_round_kernel(
    const float4* __restrict__ src, float4* __restrict__ dst)
{
    int i = blockIdx.x * 256 + threadIdx.x;
    float4 v = src[i];
    v.x = tf32_rn(v.x); v.y = tf32_rn(v.y);
    v.z = tf32_rn(v.z); v.w = tf32_rn(v.w);
    dst[i] = v;
}

// ===========================================================================
// LayerNorm over last dim (1024). One block (256 threads) per row.
// ===========================================================================
__global__ __launch_bounds__(256) void ln_kernel(
    const float* __restrict__ X, const float* __restrict__ G,
    const float* __restrict__ Bv, float* __restrict__ Y)
{
    const int row = blockIdx.x;
    const int t = threadIdx.x;
    const float4* xr = (const float4*)(X + (size_t)row * DIMC);
    float4 v = xr[t];

    float s = v.x + v.y + v.z + v.w;
    float q = v.x * v.x + v.y * v.y + v.z * v.z + v.w * v.w;
    #pragma unroll
    for (int o = 16; o > 0; o >>= 1) {
        s += __shfl_xor_sync(0xffffffffu, s, o);
        q += __shfl_xor_sync(0xffffffffu, q, o);
    }
    __shared__ float rs[8], rq[8];
    __shared__ float s_mu, s_r;
    if ((t & 31) == 0) { rs[t >> 5] = s; rq[t >> 5] = q; }
    __syncthreads();
    if (t == 0) {
        float S = 0.f, Q = 0.f;
        #pragma unroll
        for (int w = 0; w < 8; w++) { S += rs[w]; Q += rq[w]; }
        float mu  = S * (1.f / DIMC);
        float var = Q * (1.f / DIMC) - mu * mu;
        s_mu = mu;
        s_r  = rsqrtf(var + LNEPS);
    }
    __syncthreads();
    const float mu = s_mu, r = s_r;

    float4 g = ((const float4*)G)[t];
    float4 b = ((const float4*)Bv)[t];
    float4 o;
    o.x = tf32_rn((v.x - mu) * r * g.x + b.x);
    o.y = tf32_rn((v.y - mu) * r * g.y + b.y);
    o.z = tf32_rn((v.z - mu) * r * g.z + b.z);
    o.w = tf32_rn((v.w - mu) * r * g.w + b.w);
    ((float4*)(Y + (size_t)row * DIMC))[t] = o;
}

// ===========================================================================
// tf32 mma.sync GEMM: C[M,N] = A[M,1024] @ B[N,1024]^T, fp32 out.
// 128x128 block tile, 8 warps (64x32 each), BK=32, 4-stage cp.async.
// RND: round outputs to tf32 (for tensors feeding later mma ops).
// ===========================================================================
#define AS_STRIDE 36
#define TILE_FLOATS (128 * AS_STRIDE)
#define STAGE_FLOATS (2 * TILE_FLOATS)
#define NSTG 4
#define GEMM_SMEM (NSTG * STAGE_FLOATS * 4)   // 147456 B
#define KITERS (GK / 32)

__device__ __forceinline__ void stage_copy(
    const float* __restrict__ Ab, const float* __restrict__ Bb,
    uint32_t sA, uint32_t sB, int k0, int tid)
{
    #pragma unroll
    for (int i = 0; i < 4; i++) {
        const int slot = tid + i * 256;
        const int r = slot >> 3;
        const int c = slot & 7;
        const float* ga = Ab + (size_t)r * GK + k0 + c * 4;
        const float* gb = Bb + (size_t)r * GK + k0 + c * 4;
        uint32_t da = sA + (uint32_t)(r * AS_STRIDE + c * 4) * 4;
        uint32_t db = sB + (uint32_t)(r * AS_STRIDE + c * 4) * 4;
        asm volatile("cp.async.cg.shared.global [%0], [%1], 16;" :: "r"(da), "l"(ga));
        asm volatile("cp.async.cg.shared.global [%0], [%1], 16;" :: "r"(db), "l"(gb));
    }
}

template <bool RND>
__global__ __launch_bounds__(256) void gemm_tf32(
    const float* __restrict__ A, const float* __restrict__ B,
    float* __restrict__ C, int Nld)
{
    extern __shared__ __align__(16) float sm[];
    const int tid  = threadIdx.x;
    const int wid  = tid >> 5;
    const int lane = tid & 31;
    const int wm = wid >> 2;
    const int wn = wid & 3;
    const int rowBase = blockIdx.y * 128;
    const int colBase = blockIdx.x * 128;
    const float* Ab = A + (size_t)rowBase * GK;
    const float* Bb = B + (size_t)colBase * GK;

    const uint32_t sbase = (uint32_t)__cvta_generic_to_shared(sm);

    float acc[4][4][4];
    #pragma unroll
    for (int i = 0; i < 4; i++)
        #pragma unroll
        for (int j = 0; j < 4; j++)
            #pragma unroll
            for (int r = 0; r < 4; r++) acc[i][j][r] = 0.f;

    // prologue: stages 0..2
    #pragma unroll
    for (int s = 0; s < 3; s++) {
        stage_copy(Ab, Bb, sbase + (s * STAGE_FLOATS) * 4,
                   sbase + (s * STAGE_FLOATS + TILE_FLOATS) * 4, s * 32, tid);
        asm volatile("cp.async.commit_group;" ::: "memory");
    }

    const int lr = lane >> 2;
    const int lc = lane & 3;

    #pragma unroll 1
    for (int t = 0; t < KITERS; t++) {
        if (t < KITERS - 2)
            asm volatile("cp.async.wait_group 2;" ::: "memory");
        else if (t == KITERS - 2)
            asm volatile("cp.async.wait_group 1;" ::: "memory");
        else
            asm volatile("cp.async.wait_group 0;" ::: "memory");
        __syncthreads();

        if (t + 3 < KITERS) {
            const int s2 = (t + 3) & 3;
            stage_copy(Ab, Bb, sbase + (s2 * STAGE_FLOATS) * 4,
                       sbase + (s2 * STAGE_FLOATS + TILE_FLOATS) * 4,
                       (t + 3) * 32, tid);
            asm volatile("cp.async.commit_group;" ::: "memory");
        }

        const float* As = sm + (t & 3) * STAGE_FLOATS;
        const float* Bs = As + TILE_FLOATS;

        #pragma unroll
        for (int kk = 0; kk < 4; kk++) {
            const int k = kk * 8 + lc;
            uint32_t a[4][4], b[4][2];
            #pragma unroll
            for (int mt = 0; mt < 4; mt++) {
                const int m = wm * 64 + mt * 16 + lr;
                a[mt][0] = __float_as_uint(As[m * AS_STRIDE + k]);
                a[mt][1] = __float_as_uint(As[(m + 8) * AS_STRIDE + k]);
                a[mt][2] = __float_as_uint(As[m * AS_STRIDE + k + 4]);
                a[mt][3] = __float_as_uint(As[(m + 8) * AS_STRIDE + k + 4]);
            }
            #pragma unroll
            for (int nt = 0; nt < 4; nt++) {
                const int n = wn * 32 + nt * 8 + lr;
                b[nt][0] = __float_as_uint(Bs[n * AS_STRIDE + k]);
                b[nt][1] = __float_as_uint(Bs[n * AS_STRIDE + k + 4]);
            }
            #pragma unroll
            for (int mt = 0; mt < 4; mt++)
                #pragma unroll
                for (int nt = 0; nt < 4; nt++)
                    mma_tf32(acc[mt][nt], a[mt], b[nt]);
        }
    }

    #pragma unroll
    for (int mt = 0; mt < 4; mt++) {
        #pragma unroll
        for (int nt = 0; nt < 4; nt++) {
            const int row = rowBase + wm * 64 + mt * 16 + lr;
            const int col = colBase + wn * 32 + nt * 8 + 2 * lc;
            float v0 = acc[mt][nt][0], v1 = acc[mt][nt][1];
            float v2 = acc[mt][nt][2], v3 = acc[mt][nt][3];
            if (RND) { v0 = tf32_rn(v0); v1 = tf32_rn(v1);
                       v2 = tf32_rn(v2); v3 = tf32_rn(v3); }
            *(float2*)(C + (size_t)row * Nld + col)       = make_float2(v0, v1);
            *(float2*)(C + (size_t)(row + 8) * Nld + col) = make_float2(v2, v3);
        }
    }
}

// ===========================================================================
// Flash attention with tf32 mma. One block per (b,h), 8 warps x 16 rows.
// S chunked by 64; K/V double-buffered via cp.async; online softmax on
// c-fragments; P routed through per-warp smem to become an a-fragment.
// Inputs g_q/g_kv are tf32-rounded by the producing GEMMs.
// ===========================================================================
#define SC       64                      // seq chunk
#define NCHUNK   (SEQ / SC)              // 32
#define KS_STR   68
#define VS_STR   72
#define PS_STR   68
#define KS_OFF   0
#define KBUF_FL  (64 * KS_STR)           // 4352
#define VS_OFF   (2 * KBUF_FL)           // 8704
#define VBUF_FL  (64 * VS_STR)           // 4608
#define PS_OFF   (VS_OFF + 2 * VBUF_FL)  // 17920
#define ATTN_SMEM ((PS_OFF + 8 * 16 * PS_STR) * 4)   // 106496 B

__global__ __launch_bounds__(256) void attn_mma(
    const float* __restrict__ Q, const float* __restrict__ KV,
    float* __restrict__ O)
{
    extern __shared__ __align__(16) float sm[];
    const uint32_t sbase = (uint32_t)__cvta_generic_to_shared(sm);
    const int tid  = threadIdx.x;
    const int wid  = tid >> 5;
    const int lane = tid & 31;
    const int lr = lane >> 2;       // 0..7
    const int lc = lane & 3;        // 0..3
    const int b = blockIdx.x >> 4;
    const int h = blockIdx.x & 15;

    const float* kvb = KV + (size_t)b * SEQ * (2 * INNER) + h * DHEAD;

    // --- Q a-fragments: rows wid*16+{lr,lr+8}, all 64 d, scaled by 1/8 ---
    uint32_t qa[8][4];
    {
        const float* Qb = Q + ((size_t)(b * NLAT + wid * 16)) * INNER + h * DHEAD;
        #pragma unroll
        for (int kk = 0; kk < 8; kk++) {
            const int d = kk * 8 + lc;
            qa[kk][0] = __float_as_uint(Qb[(size_t)lr * INNER + d] * 0.125f);
            qa[kk][1] = __float_as_uint(Qb[(size_t)(lr + 8) * INNER + d] * 0.125f);
            qa[kk][2] = __float_as_uint(Qb[(size_t)lr * INNER + d + 4] * 0.125f);
            qa[kk][3] = __float_as_uint(Qb[(size_t)(lr + 8) * INNER + d + 4] * 0.125f);
        }
    }

    float o[8][4];
    #pragma unroll
    for (int nt = 0; nt < 8; nt++)
        #pragma unroll
        for (int r = 0; r < 4; r++) o[nt][r] = 0.f;
    float m0 = -1e30f, m1 = -1e30f, l0 = 0.f, l1 = 0.f;

    // chunk loader (K + V, 4 float4 each per thread)
    auto load_chunk = [&](int s0, int buf) {
        #pragma unroll
        for (int i = 0; i < 4; i++) {
            const int slot = tid + i * 256;       // 0..1023
            const int r = slot >> 4;              // 0..63
            const int c = slot & 15;              // 0..15
            const float* gk = kvb + (size_t)(s0 + r) * (2 * INNER) + c * 4;
            uint32_t dk = sbase + (uint32_t)(KS_OFF + buf * KBUF_FL + r * KS_STR + c * 4) * 4;
            uint32_t dv = sbase + (uint32_t)(VS_OFF + buf * VBUF_FL + r * VS_STR + c * 4) * 4;
            asm volatile("cp.async.cg.shared.global [%0], [%1], 16;" :: "r"(dk), "l"(gk));
            asm volatile("cp.async.cg.shared.global [%0], [%1], 16;" :: "r"(dv), "l"(gk + INNER));
        }
    };

    load_chunk(0, 0);
    asm volatile("cp.async.commit_group;" ::: "memory");

    float* Ps = sm + PS_OFF + wid * (16 * PS_STR);

    #pragma unroll 1
    for (int c = 0; c < NCHUNK; c++) {
        const int buf = c & 1;
        __syncthreads();                       // everyone done with buf^1
        if (c + 1 < NCHUNK) {
            load_chunk((c + 1) * SC, buf ^ 1);
            asm volatile("cp.async.commit_group;" ::: "memory");
            asm volatile("cp.async.wait_group 1;" ::: "memory");
        } else {
            asm volatile("cp.async.wait_group 0;" ::: "memory");
        }
        __syncthreads();                       // chunk c visible to all

        const uint32_t* Ku = (const uint32_t*)(sm + KS_OFF + buf * KBUF_FL);
        const float*    Vs = sm + VS_OFF + buf * VBUF_FL;

        // ---- S = Q @ K^T  (16 x 64 per warp) ----
        float sc[8][4];
        #pragma unroll
        for (int nt = 0; nt < 8; nt++)
            #pragma unroll
            for (int r = 0; r < 4; r++) sc[nt][r] = 0.f;

        #pragma unroll
        for (int kk = 0; kk < 8; kk++) {
            const int kb = kk * 8 + lc;
            uint32_t bb[8][2];
            #pragma unroll
            for (int nt = 0; nt < 8; nt++) {
                bb[nt][0] = Ku[(nt * 8 + lr) * KS_STR + kb];
                bb[nt][1] = Ku[(nt * 8 + lr) * KS_STR + kb + 4];
            }
            #pragma unroll
            for (int nt = 0; nt < 8; nt++)
                mma_tf32(sc[nt], qa[kk], bb[nt]);
        }

        // ---- online softmax (rows lr and lr+8) ----
        float mx0 = -1e30f, mx1 = -1e30f;
        #pragma unroll
        for (int nt = 0; nt < 8; nt++) {
            mx0 = fmaxf(mx0, fmaxf(sc[nt][0], sc[nt][1]));
            mx1 = fmaxf(mx1, fmaxf(sc[nt][2], sc[nt][3]));
        }
        #pragma unroll
        for (int off = 1; off <= 2; off <<= 1) {
            mx0 = fmaxf(mx0, __shfl_xor_sync(0xffffffffu, mx0, off));
            mx1 = fmaxf(mx1, __shfl_xor_sync(0xffffffffu, mx1, off));
        }
        const float nm0 = fmaxf(m0, mx0);
        const float nm1 = fmaxf(m1, mx1);
        const float cr0 = __expf(m0 - nm0);
        const float cr1 = __expf(m1 - nm1);
        m0 = nm0; m1 = nm1;

        float rs0 = 0.f, rs1 = 0.f;
        #pragma unroll
        for (int nt = 0; nt < 8; nt++) {
            float p0 = __expf(sc[nt][0] - nm0);
            float p1 = __expf(sc[nt][1] - nm0);
            float p2 = __expf(sc[nt][2] - nm1);
            float p3 = __expf(sc[nt][3] - nm1);
            rs0 += p0 + p1;
            rs1 += p2 + p3;
            const int col = nt * 8 + 2 * lc;
            Ps[lr * PS_STR + col]           = tf32_rn(p0);
            Ps[lr * PS_STR + col + 1]       = tf32_rn(p1);
            Ps[(lr + 8) * PS_STR + col]     = tf32_rn(p2);
            Ps[(lr + 8) * PS_STR + col + 1] = tf32_rn(p3);
        }
        #pragma unroll
        for (int off = 1; off <= 2; off <<= 1) {
            rs0 += __shfl_xor_sync(0xffffffffu, rs0, off);
            rs1 += __shfl_xor_sync(0xffffffffu, rs1, off);
        }
        l0 = l0 * cr0 + rs0;
        l1 = l1 * cr1 + rs1;
        #pragma unroll
        for (int nt = 0; nt < 8; nt++) {
            o[nt][0] *= cr0; o[nt][1] *= cr0;
            o[nt][2] *= cr1; o[nt][3] *= cr1;
        }
        __syncwarp();

        // ---- O += P @ V ----
        const uint32_t* Pu = (const uint32_t*)Ps;
        const uint32_t* Vu = (const uint32_t*)Vs;
        #pragma unroll
        for (int kk = 0; kk < 8; kk++) {
            const int j = kk * 8 + lc;
            uint32_t a[4];
            a[0] = Pu[lr * PS_STR + j];
            a[1] = Pu[(lr + 8) * PS_STR + j];
            a[2] = Pu[lr * PS_STR + j + 4];
            a[3] = Pu[(lr + 8) * PS_STR + j + 4];
            uint32_t bb[8][2];
            #pragma unroll
            for (int nt = 0; nt < 8; nt++) {
                bb[nt][0] = Vu[j * VS_STR + nt * 8 + lr];
                bb[nt][1] = Vu[(j + 4) * VS_STR + nt * 8 + lr];
            }
            #pragma unroll
            for (int nt = 0; nt < 8; nt++)
                mma_tf32(o[nt], a, bb[nt]);
        }
    }

    // ---- epilogue ----
    const float inv0 = 1.f / l0;
    const float inv1 = 1.f / l1;
    float* Ob = O + ((size_t)(b * NLAT + wid * 16)) * INNER + h * DHEAD;
    #pragma unroll
    for (int nt = 0; nt < 8; nt++) {
        const int col = nt * 8 + 2 * lc;
        float v0 = tf32_rn(o[nt][0] * inv0);
        float v1 = tf32_rn(o[nt][1] * inv0);
        float v2 = tf32_rn(o[nt][2] * inv1);
        float v3 = tf32_rn(o[nt][3] * inv1);
        *(float2*)(Ob + (size_t)lr * INNER + col)       = make_float2(v0, v1);
        *(float2*)(Ob + (size_t)(lr + 8) * INNER + col) = make_float2(v2, v3);
    }
}

// ===========================================================================
// launch
// ===========================================================================
extern "C" void kernel_launch(void* const* d_in, const int* in_sizes, int n_in,
                              void* d_out, int out_size)
{
    (void)in_sizes; (void)n_in; (void)out_size;
    const float* x   = (const float*)d_in[0];
    const float* lat = (const float*)d_in[1];
    const float* gx  = (const float*)d_in[2];
    const float* bx  = (const float*)d_in[3];
    const float* gl  = (const float*)d_in[4];
    const float* bl  = (const float*)d_in[5];
    const float* Wq  = (const float*)d_in[6];
    const float* Wkv = (const float*)d_in[7];
    const float* Wo  = (const float*)d_in[8];
    float* out = (float*)d_out;

    float *p_xn, *p_ln, *p_kv, *p_q, *p_att, *p_wq, *p_wkv, *p_wo;
    cudaGetSymbolAddress((void**)&p_xn,  g_xn);
    cudaGetSymbolAddress((void**)&p_ln,  g_ln);
    cudaGetSymbolAddress((void**)&p_kv,  g_kv);
    cudaGetSymbolAddress((void**)&p_q,   g_q);
    cudaGetSymbolAddress((void**)&p_att, g_att);
    cudaGetSymbolAddress((void**)&p_wq,  g_wq);
    cudaGetSymbolAddress((void**)&p_wkv, g_wkv);
    cudaGetSymbolAddress((void**)&p_wo,  g_wo);

    static int smem_set = 0;
    if (!smem_set) {
        cudaFuncSetAttribute(gemm_tf32<true>,  cudaFuncAttributeMaxDynamicSharedMemorySize, GEMM_SMEM);
        cudaFuncSetAttribute(gemm_tf32<false>, cudaFuncAttributeMaxDynamicSharedMemorySize, GEMM_SMEM);
        cudaFuncSetAttribute(attn_mma, cudaFuncAttributeMaxDynamicSharedMemorySize, ATTN_SMEM);
        smem_set = 1;
    }

    const int rowsX = BATCH * SEQ;    // 32768
    const int rowsL = BATCH * NLAT;   // 2048

    ln_kernel<<<rowsX, 256>>>(x,   gx, bx, p_xn);
    ln_kernel<<<rowsL, 256>>>(lat, gl, bl, p_ln);

    tf32_round_kernel<<<(2 * INNER * DIMC) / 1024, 256>>>((const float4*)Wkv, (float4*)p_wkv);
    tf32_round_kernel<<<(INNER * DIMC) / 1024, 256>>>((const float4*)Wq, (float4*)p_wq);
    tf32_round_kernel<<<(DIMC * INNER) / 1024, 256>>>((const float4*)Wo, (float4*)p_wo);

    gemm_tf32<true><<<dim3(2 * INNER / 128, rowsX / 128), 256, GEMM_SMEM>>>(p_xn, p_wkv, p_kv, 2 * INNER);
    gemm_tf32<true><<<dim3(INNER / 128, rowsL / 128), 256, GEMM_SMEM>>>(p_ln, p_wq, p_q, INNER);

    attn_mma<<<BATCH * HEADS, 256, ATTN_SMEM>>>(p_q, p_kv, p_att);

    gemm_tf32<false><<<dim3(DIMC / 128, rowsL / 128), 256, GEMM_SMEM>>>(p_att, p_wo, out, DIMC);
}

// round 7
// speedup vs baseline: 7.5254x; 2.0257x over previous
#include <cuda_runtime.h>
#include <cuda_fp16.h>
#include <cstdint>
#include <cstddef>

// ---------------------------------------------------------------------------
// PerceiverAttention: fp16 mma.sync (m16n8k16) GEMMs + fp16 flash-attention.
//   B=16, S=2048, M=128, DIM=1024, HEADS=16, DIM_HEAD=64, INNER=1024
// fp16 mantissa (10b) == tf32 mantissa => same rounding error, 2x throughput.
// All accumulation in fp32.
// ---------------------------------------------------------------------------

#define DIMC     1024
#define BATCH    16
#define SEQ      2048
#define NLAT     128
#define HEADS    16
#define DHEAD    64
#define INNER    1024
#define LNEPS    1e-5f
#define GK       1024

__device__ __half g_xn [(size_t)BATCH * SEQ * DIMC];
__device__ __half g_ln [(size_t)BATCH * NLAT * DIMC];
__device__ __half g_kv [(size_t)BATCH * SEQ * 2 * INNER];
__device__ __half g_q  [(size_t)BATCH * NLAT * INNER];
__device__ __half g_att[(size_t)BATCH * NLAT * INNER];
__device__ __half g_wq [(size_t)INNER * DIMC];
__device__ __half g_wkv[(size_t)2 * INNER * DIMC];
__device__ __half g_wo [(size_t)DIMC * INNER];

// ---------------------------------------------------------------------------
// helpers
// ---------------------------------------------------------------------------
__device__ __forceinline__ void mma_fp16(
    float* c, const uint32_t* a, const uint32_t* b)
{
    asm volatile(
        "mma.sync.aligned.m16n8k16.row.col.f32.f16.f16.f32 "
        "{%0,%1,%2,%3}, {%4,%5,%6,%7}, {%8,%9}, {%0,%1,%2,%3};"
        : "+f"(c[0]), "+f"(c[1]), "+f"(c[2]), "+f"(c[3])
        : "r"(a[0]), "r"(a[1]), "r"(a[2]), "r"(a[3]), "r"(b[0]), "r"(b[1]));
}

#define LDSM_X4(r0, r1, r2, r3, addr) \
    asm volatile("ldmatrix.sync.aligned.m8n8.x4.shared.b16 {%0,%1,%2,%3}, [%4];" \
        : "=r"(r0), "=r"(r1), "=r"(r2), "=r"(r3) : "r"(addr))

#define LDSM_X4_T(r0, r1, r2, r3, addr) \
    asm volatile("ldmatrix.sync.aligned.m8n8.x4.trans.shared.b16 {%0,%1,%2,%3}, [%4];" \
        : "=r"(r0), "=r"(r1), "=r"(r2), "=r"(r3) : "r"(addr))

__device__ __forceinline__ uint32_t h2u(__half2 h) {
    return *reinterpret_cast<uint32_t*>(&h);
}

// ===========================================================================
// fp32 -> fp16 weight conversion (float4 -> 4 halves)
// ===========================================================================
__global__ __launch_bounds__(256) void h_convert_kernel(
    const float4* __restrict__ src, uint2* __restrict__ dst)
{
    int i = blockIdx.x * 256 + threadIdx.x;
    float4 v = src[i];
    uint2 o;
    o.x = h2u(__floats2half2_rn(v.x, v.y));
    o.y = h2u(__floats2half2_rn(v.z, v.w));
    dst[i] = o;
}

// ===========================================================================
// LayerNorm (1024) -> fp16 output. One block (256 threads) per row.
// ===========================================================================
__global__ __launch_bounds__(256) void ln_kernel(
    const float* __restrict__ X, const float* __restrict__ G,
    const float* __restrict__ Bv, __half* __restrict__ Y)
{
    const int row = blockIdx.x;
    const int t = threadIdx.x;
    const float4* xr = (const float4*)(X + (size_t)row * DIMC);
    float4 v = xr[t];

    float s = v.x + v.y + v.z + v.w;
    float q = v.x * v.x + v.y * v.y + v.z * v.z + v.w * v.w;
    #pragma unroll
    for (int o = 16; o > 0; o >>= 1) {
        s += __shfl_xor_sync(0xffffffffu, s, o);
        q += __shfl_xor_sync(0xffffffffu, q, o);
    }
    __shared__ float rs[8], rq[8];
    __shared__ float s_mu, s_r;
    if ((t & 31) == 0) { rs[t >> 5] = s; rq[t >> 5] = q; }
    __syncthreads();
    if (t == 0) {
        float S = 0.f, Q = 0.f;
        #pragma unroll
        for (int w = 0; w < 8; w++) { S += rs[w]; Q += rq[w]; }
        float mu  = S * (1.f / DIMC);
        float var = Q * (1.f / DIMC) - mu * mu;
        s_mu = mu;
        s_r  = rsqrtf(var + LNEPS);
    }
    __syncthreads();
    const float mu = s_mu, r = s_r;

    float4 g = ((const float4*)G)[t];
    float4 b = ((const float4*)Bv)[t];
    uint2 o;
    o.x = h2u(__floats2half2_rn((v.x - mu) * r * g.x + b.x,
                                (v.y - mu) * r * g.y + b.y));
    o.y = h2u(__floats2half2_rn((v.z - mu) * r * g.z + b.z,
                                (v.w - mu) * r * g.w + b.w));
    ((uint2*)(Y + (size_t)row * DIMC))[t] = o;
}

// ===========================================================================
// fp16 mma GEMM: C[M,N] = A[M,1024] @ B[N,1024]^T.
// 128x128 block tile, 8 warps (64x32), BK=32 halves, 4-stage cp.async,
// ldmatrix fragment loads. OutT = __half or float.
// ===========================================================================
#define HSTR 40                          // halves per smem row (32 + 8 pad)
#define TILE_H (128 * HSTR)              // 5120 halves
#define STAGE_H (2 * TILE_H)
#define NSTG 4
#define GEMM_SMEM (NSTG * STAGE_H * 2)   // 81920 B
#define KITERS (GK / 32)                 // 32

__device__ __forceinline__ void stage_copy_h(
    const __half* __restrict__ Ab, const __half* __restrict__ Bb,
    uint32_t sA, uint32_t sB, int k0, int tid)
{
    #pragma unroll
    for (int i = 0; i < 2; i++) {
        const int slot = tid + i * 256;        // 0..511
        const int r = slot >> 2;               // row 0..127
        const int c = slot & 3;                // 8-half chunk 0..3
        const __half* ga = Ab + (size_t)r * GK + k0 + c * 8;
        const __half* gb = Bb + (size_t)r * GK + k0 + c * 8;
        uint32_t da = sA + (uint32_t)(r * HSTR + c * 8) * 2;
        uint32_t db = sB + (uint32_t)(r * HSTR + c * 8) * 2;
        asm volatile("cp.async.cg.shared.global [%0], [%1], 16;" :: "r"(da), "l"(ga));
        asm volatile("cp.async.cg.shared.global [%0], [%1], 16;" :: "r"(db), "l"(gb));
    }
}

template <typename OutT>
__global__ __launch_bounds__(256) void gemm_h(
    const __half* __restrict__ A, const __half* __restrict__ B,
    OutT* __restrict__ C, int Nld)
{
    extern __shared__ __align__(16) __half smh[];
    const int tid  = threadIdx.x;
    const int wid  = tid >> 5;
    const int lane = tid & 31;
    const int wm = wid >> 2;                 // 0..1
    const int wn = wid & 3;                  // 0..3
    const int rowBase = blockIdx.y * 128;
    const int colBase = blockIdx.x * 128;
    const __half* Ab = A + (size_t)rowBase * GK;
    const __half* Bb = B + (size_t)colBase * GK;

    const uint32_t sbase = (uint32_t)__cvta_generic_to_shared(smh);

    float acc[4][4][4];
    #pragma unroll
    for (int i = 0; i < 4; i++)
        #pragma unroll
        for (int j = 0; j < 4; j++)
            #pragma unroll
            for (int r = 0; r < 4; r++) acc[i][j][r] = 0.f;

    #pragma unroll
    for (int s = 0; s < 3; s++) {
        stage_copy_h(Ab, Bb, sbase + (s * STAGE_H) * 2,
                     sbase + (s * STAGE_H + TILE_H) * 2, s * 32, tid);
        asm volatile("cp.async.commit_group;" ::: "memory");
    }

    const int lr = lane >> 2;
    const int lc = lane & 3;
    // ldmatrix lane address components
    const int aRow = wm * 64 + (lane & 15);
    const int aK   = (lane >> 4) << 3;
    const int bRow = wn * 32 + (lane & 7) + ((lane >> 4) << 3);
    const int bK   = ((lane >> 3) & 1) << 3;

    #pragma unroll 1
    for (int t = 0; t < KITERS; t++) {
        if (t < KITERS - 2)
            asm volatile("cp.async.wait_group 2;" ::: "memory");
        else if (t == KITERS - 2)
            asm volatile("cp.async.wait_group 1;" ::: "memory");
        else
            asm volatile("cp.async.wait_group 0;" ::: "memory");
        __syncthreads();

        if (t + 3 < KITERS) {
            const int s2 = (t + 3) & 3;
            stage_copy_h(Ab, Bb, sbase + (s2 * STAGE_H) * 2,
                         sbase + (s2 * STAGE_H + TILE_H) * 2, (t + 3) * 32, tid);
            asm volatile("cp.async.commit_group;" ::: "memory");
        }

        const uint32_t sAs = sbase + ((t & 3) * STAGE_H) * 2;
        const uint32_t sBs = sAs + TILE_H * 2;

        #pragma unroll
        for (int kk = 0; kk < 2; kk++) {
            const int k16 = kk * 16;
            uint32_t a[4][4], b[4][2];
            #pragma unroll
            for (int mt = 0; mt < 4; mt++) {
                uint32_t ad = sAs + (uint32_t)((aRow + mt * 16) * HSTR + k16 + aK) * 2;
                LDSM_X4(a[mt][0], a[mt][1], a[mt][2], a[mt][3], ad);
            }
            #pragma unroll
            for (int g = 0; g < 2; g++) {
                uint32_t bd = sBs + (uint32_t)((bRow + g * 16) * HSTR + k16 + bK) * 2;
                LDSM_X4(b[2 * g][0], b[2 * g][1], b[2 * g + 1][0], b[2 * g + 1][1], bd);
            }
            #pragma unroll
            for (int mt = 0; mt < 4; mt++)
                #pragma unroll
                for (int nt = 0; nt < 4; nt++)
                    mma_fp16(acc[mt][nt], a[mt], b[nt]);
        }
    }

    #pragma unroll
    for (int mt = 0; mt < 4; mt++) {
        #pragma unroll
        for (int nt = 0; nt < 4; nt++) {
            const int row = rowBase + wm * 64 + mt * 16 + lr;
            const int col = colBase + wn * 32 + nt * 8 + 2 * lc;
            if constexpr (sizeof(OutT) == 2) {
                __half* Ch = (__half*)C;
                *(uint32_t*)(Ch + (size_t)row * Nld + col) =
                    h2u(__floats2half2_rn(acc[mt][nt][0], acc[mt][nt][1]));
                *(uint32_t*)(Ch + (size_t)(row + 8) * Nld + col) =
                    h2u(__floats2half2_rn(acc[mt][nt][2], acc[mt][nt][3]));
            } else {
                float* Cf = (float*)C;
                *(float2*)(Cf + (size_t)row * Nld + col) =
                    make_float2(acc[mt][nt][0], acc[mt][nt][1]);
                *(float2*)(Cf + (size_t)(row + 8) * Nld + col) =
                    make_float2(acc[mt][nt][2], acc[mt][nt][3]);
            }
        }
    }
}

// ===========================================================================
// fp16 flash attention. One block per (b,h), 8 warps x 16 latent rows.
// S chunked by 64, K/V double-buffered cp.async, softmax stats fp32,
// P through per-warp smem (half), V fragments via ldmatrix.trans.
// ===========================================================================
#define SC     64
#define NCHUNK (SEQ / SC)                // 32
#define KVSTR  72                        // halves per K/V smem row
#define KBUF_H (64 * KVSTR)              // 4608 halves
#define VS_H   (2 * KBUF_H)              // 9216
#define PS_H   (VS_H + 2 * KBUF_H)       // 18432
#define PSTR   72
#define ATTN_SMEM ((PS_H + 8 * 16 * PSTR) * 2)   // 55296 B

__global__ __launch_bounds__(256) void attn_mma(
    const __half* __restrict__ Q, const __half* __restrict__ KV,
    __half* __restrict__ O)
{
    extern __shared__ __align__(16) __half smh[];
    const uint32_t sbase = (uint32_t)__cvta_generic_to_shared(smh);
    const int tid  = threadIdx.x;
    const int wid  = tid >> 5;
    const int lane = tid & 31;
    const int lr = lane >> 2;
    const int lc = lane & 3;
    const int b = blockIdx.x >> 4;
    const int h = blockIdx.x & 15;

    const __half* kvb = KV + (size_t)b * SEQ * (2 * INNER) + h * DHEAD;

    // Q a-fragments (4 k16 steps over d=64), scaled by 1/8 (exact in fp16)
    uint32_t qa[4][4];
    {
        const __half* Qb = Q + ((size_t)(b * NLAT + wid * 16)) * INNER + h * DHEAD;
        const __half2 s2 = __float2half2_rn(0.125f);
        #pragma unroll
        for (int kk = 0; kk < 4; kk++) {
            const int d = kk * 16 + 2 * lc;
            __half2 v;
            v = *(const __half2*)(Qb + (size_t)lr * INNER + d);       qa[kk][0] = h2u(__hmul2(v, s2));
            v = *(const __half2*)(Qb + (size_t)(lr + 8) * INNER + d); qa[kk][1] = h2u(__hmul2(v, s2));
            v = *(const __half2*)(Qb + (size_t)lr * INNER + d + 8);       qa[kk][2] = h2u(__hmul2(v, s2));
            v = *(const __half2*)(Qb + (size_t)(lr + 8) * INNER + d + 8); qa[kk][3] = h2u(__hmul2(v, s2));
        }
    }

    float o[8][4];
    #pragma unroll
    for (int nt = 0; nt < 8; nt++)
        #pragma unroll
        for (int r = 0; r < 4; r++) o[nt][r] = 0.f;
    float m0 = -1e30f, m1 = -1e30f, l0 = 0.f, l1 = 0.f;

    auto load_chunk = [&](int s0, int buf) {
        #pragma unroll
        for (int i = 0; i < 2; i++) {
            const int slot = tid + i * 256;     // 0..511
            const int r = slot >> 3;            // 0..63
            const int c = slot & 7;             // 8-half chunk
            const __half* gk = kvb + (size_t)(s0 + r) * (2 * INNER) + c * 8;
            uint32_t dk = sbase + (uint32_t)(buf * KBUF_H + r * KVSTR + c * 8) * 2;
            uint32_t dv = sbase + (uint32_t)(VS_H + buf * KBUF_H + r * KVSTR + c * 8) * 2;
            asm volatile("cp.async.cg.shared.global [%0], [%1], 16;" :: "r"(dk), "l"(gk));
            asm volatile("cp.async.cg.shared.global [%0], [%1], 16;" :: "r"(dv), "l"(gk + INNER));
        }
    };

    load_chunk(0, 0);
    asm volatile("cp.async.commit_group;" ::: "memory");

    __half* Ps = smh + PS_H + wid * (16 * PSTR);
    uint32_t* Pu = (uint32_t*)Ps;
    // K b-frag ldmatrix lane components (same as GEMM B)
    const int kRow = (lane & 7) + ((lane >> 4) << 3);
    const int kK   = ((lane >> 3) & 1) << 3;
    // V trans ldmatrix lane components
    const int vmi = lane >> 3;
    const int vJ  = ((vmi & 1) << 3) + (lane & 7);
    const int vD  = (vmi >> 1) << 3;

    #pragma unroll 1
    for (int c = 0; c < NCHUNK; c++) {
        const int buf = c & 1;
        __syncthreads();
        if (c + 1 < NCHUNK) {
            load_chunk((c + 1) * SC, buf ^ 1);
            asm volatile("cp.async.commit_group;" ::: "memory");
            asm volatile("cp.async.wait_group 1;" ::: "memory");
        } else {
            asm volatile("cp.async.wait_group 0;" ::: "memory");
        }
        __syncthreads();

        const uint32_t Kb = sbase + (uint32_t)(buf * KBUF_H) * 2;
        const uint32_t Vb = sbase + (uint32_t)(VS_H + buf * KBUF_H) * 2;

        // ---- S = Q @ K^T (16 x 64 per warp) ----
        float sc[8][4];
        #pragma unroll
        for (int nt = 0; nt < 8; nt++)
            #pragma unroll
            for (int r = 0; r < 4; r++) sc[nt][r] = 0.f;

        #pragma unroll
        for (int kk = 0; kk < 4; kk++) {
            const int k16 = kk * 16;
            uint32_t bb[8][2];
            #pragma unroll
            for (int g = 0; g < 4; g++) {
                uint32_t ad = Kb + (uint32_t)((g * 16 + kRow) * KVSTR + k16 + kK) * 2;
                LDSM_X4(bb[2 * g][0], bb[2 * g][1], bb[2 * g + 1][0], bb[2 * g + 1][1], ad);
            }
            #pragma unroll
            for (int nt = 0; nt < 8; nt++)
                mma_fp16(sc[nt], qa[kk], bb[nt]);
        }

        // ---- online softmax ----
        float mx0 = -1e30f, mx1 = -1e30f;
        #pragma unroll
        for (int nt = 0; nt < 8; nt++) {
            mx0 = fmaxf(mx0, fmaxf(sc[nt][0], sc[nt][1]));
            mx1 = fmaxf(mx1, fmaxf(sc[nt][2], sc[nt][3]));
        }
        #pragma unroll
        for (int off = 1; off <= 2; off <<= 1) {
            mx0 = fmaxf(mx0, __shfl_xor_sync(0xffffffffu, mx0, off));
            mx1 = fmaxf(mx1, __shfl_xor_sync(0xffffffffu, mx1, off));
        }
        const float nm0 = fmaxf(m0, mx0);
        const float nm1 = fmaxf(m1, mx1);
        const float cr0 = __expf(m0 - nm0);
        const float cr1 = __expf(m1 - nm1);
        m0 = nm0; m1 = nm1;

        float rs0 = 0.f, rs1 = 0.f;
        #pragma unroll
        for (int nt = 0; nt < 8; nt++) {
            float p0 = __expf(sc[nt][0] - nm0);
            float p1 = __expf(sc[nt][1] - nm0);
            float p2 = __expf(sc[nt][2] - nm1);
            float p3 = __expf(sc[nt][3] - nm1);
            rs0 += p0 + p1;
            rs1 += p2 + p3;
            Pu[lr * (PSTR / 2) + nt * 4 + lc]       = h2u(__floats2half2_rn(p0, p1));
            Pu[(lr + 8) * (PSTR / 2) + nt * 4 + lc] = h2u(__floats2half2_rn(p2, p3));
        }
        #pragma unroll
        for (int off = 1; off <= 2; off <<= 1) {
            rs0 += __shfl_xor_sync(0xffffffffu, rs0, off);
            rs1 += __shfl_xor_sync(0xffffffffu, rs1, off);
        }
        l0 = l0 * cr0 + rs0;
        l1 = l1 * cr1 + rs1;
        #pragma unroll
        for (int nt = 0; nt < 8; nt++) {
            o[nt][0] *= cr0; o[nt][1] *= cr0;
            o[nt][2] *= cr1; o[nt][3] *= cr1;
        }
        __syncwarp();

        // ---- O += P @ V ----
        #pragma unroll
        for (int kk = 0; kk < 4; kk++) {
            uint32_t pa[4];
            pa[0] = Pu[lr * (PSTR / 2) + kk * 8 + lc];
            pa[1] = Pu[(lr + 8) * (PSTR / 2) + kk * 8 + lc];
            pa[2] = Pu[lr * (PSTR / 2) + kk * 8 + lc + 4];
            pa[3] = Pu[(lr + 8) * (PSTR / 2) + kk * 8 + lc + 4];
            uint32_t vb[8][2];
            #pragma unroll
            for (int g = 0; g < 4; g++) {
                uint32_t ad = Vb + (uint32_t)((kk * 16 + vJ) * KVSTR + g * 16 + vD) * 2;
                LDSM_X4_T(vb[2 * g][0], vb[2 * g][1], vb[2 * g + 1][0], vb[2 * g + 1][1], ad);
            }
            #pragma unroll
            for (int nt = 0; nt < 8; nt++)
                mma_fp16(o[nt], pa, vb[nt]);
        }
        __syncwarp();
    }

    // ---- epilogue: O /= l, store half ----
    const float inv0 = 1.f / l0;
    const float inv1 = 1.f / l1;
    __half* Ob = O + ((size_t)(b * NLAT + wid * 16)) * INNER + h * DHEAD;
    #pragma unroll
    for (int nt = 0; nt < 8; nt++) {
        const int col = nt * 8 + 2 * lc;
        *(uint32_t*)(Ob + (size_t)lr * INNER + col) =
            h2u(__floats2half2_rn(o[nt][0] * inv0, o[nt][1] * inv0));
        *(uint32_t*)(Ob + (size_t)(lr + 8) * INNER + col) =
            h2u(__floats2half2_rn(o[nt][2] * inv1, o[nt][3] * inv1));
    }
}

// ===========================================================================
// launch
// ===========================================================================
extern "C" void kernel_launch(void* const* d_in, const int* in_sizes, int n_in,
                              void* d_out, int out_size)
{
    (void)in_sizes; (void)n_in; (void)out_size;
    const float* x   = (const float*)d_in[0];
    const float* lat = (const float*)d_in[1];
    const float* gx  = (const float*)d_in[2];
    const float* bx  = (const float*)d_in[3];
    const float* gl  = (const float*)d_in[4];
    const float* bl  = (const float*)d_in[5];
    const float* Wq  = (const float*)d_in[6];
    const float* Wkv = (const float*)d_in[7];
    const float* Wo  = (const float*)d_in[8];
    float* out = (float*)d_out;

    __half *p_xn, *p_ln, *p_kv, *p_q, *p_att, *p_wq, *p_wkv, *p_wo;
    cudaGetSymbolAddress((void**)&p_xn,  g_xn);
    cudaGetSymbolAddress((void**)&p_ln,  g_ln);
    cudaGetSymbolAddress((void**)&p_kv,  g_kv);
    cudaGetSymbolAddress((void**)&p_q,   g_q);
    cudaGetSymbolAddress((void**)&p_att, g_att);
    cudaGetSymbolAddress((void**)&p_wq,  g_wq);
    cudaGetSymbolAddress((void**)&p_wkv, g_wkv);
    cudaGetSymbolAddress((void**)&p_wo,  g_wo);

    // idempotent, capture-safe host attribute sets (no static guards per rules)
    cudaFuncSetAttribute(gemm_h<__half>, cudaFuncAttributeMaxDynamicSharedMemorySize, GEMM_SMEM);
    cudaFuncSetAttribute(gemm_h<float>,  cudaFuncAttributeMaxDynamicSharedMemorySize, GEMM_SMEM);
    cudaFuncSetAttribute(attn_mma, cudaFuncAttributeMaxDynamicSharedMemorySize, ATTN_SMEM);

    const int rowsX = BATCH * SEQ;    // 32768
    const int rowsL = BATCH * NLAT;   // 2048

    ln_kernel<<<rowsX, 256>>>(x,   gx, bx, p_xn);
    ln_kernel<<<rowsL, 256>>>(lat, gl, bl, p_ln);

    h_convert_kernel<<<(2 * INNER * DIMC) / 1024, 256>>>((const float4*)Wkv, (uint2*)p_wkv);
    h_convert_kernel<<<(INNER * DIMC) / 1024, 256>>>((const float4*)Wq, (uint2*)p_wq);
    h_convert_kernel<<<(DIMC * INNER) / 1024, 256>>>((const float4*)Wo, (uint2*)p_wo);

    gemm_h<__half><<<dim3(2 * INNER / 128, rowsX / 128), 256, GEMM_SMEM>>>(p_xn, p_wkv, p_kv, 2 * INNER);
    gemm_h<__half><<<dim3(INNER / 128, rowsL / 128), 256, GEMM_SMEM>>>(p_ln, p_wq, p_q, INNER);

    attn_mma<<<BATCH * HEADS, 256, ATTN_SMEM>>>(p_q, p_kv, p_att);

    gemm_h<float><<<dim3(DIMC / 128, rowsL / 128), 256, GEMM_SMEM>>>(p_att, p_wo, out, DIMC);
}